// round 3
// baseline (speedup 1.0000x reference)
#include <cuda_runtime.h>
#include <cuda_bf16.h>
#include <math.h>

// Problem constants: B=1, S=2048, D=2048, 32 heads, hd=64, 8 KV heads (GQA rep=4)
#define S_LEN 2048
#define DMODEL 2048
#define NKV_D 512          // N_KV_HEADS * hd = 8*64
#define HD 64
#define NHEADS 32

// -------- scratch (no allocations allowed; device globals) --------
__device__ float g_Q[S_LEN * DMODEL];   // 16 MB
__device__ float g_K[S_LEN * NKV_D];    // 4 MB
__device__ float g_V[S_LEN * NKV_D];    // 4 MB
__device__ float g_Y[S_LEN * DMODEL];   // 16 MB

// ============================================================================
// Tiled fp32 GEMM: C[M,N] = A[M,K] * B[K,N], all row-major.
// 128x128 block tile, BK=16, 8x8 per thread, 256 threads.
// Requires M%128==0, N%128==0... (N=512 ok: grid handles), K%16==0.
// ============================================================================
#define GBM 128
#define GBN 128
#define GBK 16

__global__ __launch_bounds__(256) void gemm_kernel(
    const float* __restrict__ A, const float* __restrict__ B,
    float* __restrict__ C, int M, int N, int K)
{
    __shared__ float As[GBK][GBM];   // transposed A tile
    __shared__ float Bs[GBK][GBN];

    const int tid = threadIdx.x;
    const int bm = blockIdx.y * GBM;
    const int bn = blockIdx.x * GBN;
    const int tr = (tid / 16) * 8;
    const int tc = (tid % 16) * 8;

    float acc[8][8];
#pragma unroll
    for (int i = 0; i < 8; i++)
#pragma unroll
        for (int j = 0; j < 8; j++) acc[i][j] = 0.f;

    for (int k0 = 0; k0 < K; k0 += GBK) {
        // load A tile (128 x 16): 512 float4, 2 per thread, store transposed
#pragma unroll
        for (int i = 0; i < 2; i++) {
            int id = tid + i * 256;
            int row = id >> 2;            // 0..127
            int col = (id & 3) * 4;       // 0,4,8,12
            float4 a = *(const float4*)&A[(size_t)(bm + row) * K + k0 + col];
            As[col + 0][row] = a.x;
            As[col + 1][row] = a.y;
            As[col + 2][row] = a.z;
            As[col + 3][row] = a.w;
        }
        // load B tile (16 x 128): 512 float4, 2 per thread
#pragma unroll
        for (int i = 0; i < 2; i++) {
            int id = tid + i * 256;
            int row = id >> 5;            // 0..15
            int col = (id & 31) * 4;      // 0..124
            *(float4*)&Bs[row][col] =
                *(const float4*)&B[(size_t)(k0 + row) * N + bn + col];
        }
        __syncthreads();

#pragma unroll
        for (int k = 0; k < GBK; k++) {
            float a[8], b[8];
            *(float4*)&a[0] = *(float4*)&As[k][tr];
            *(float4*)&a[4] = *(float4*)&As[k][tr + 4];
            *(float4*)&b[0] = *(float4*)&Bs[k][tc];
            *(float4*)&b[4] = *(float4*)&Bs[k][tc + 4];
#pragma unroll
            for (int i = 0; i < 8; i++)
#pragma unroll
                for (int j = 0; j < 8; j++)
                    acc[i][j] += a[i] * b[j];
        }
        __syncthreads();
    }

#pragma unroll
    for (int i = 0; i < 8; i++) {
        float4 c0 = make_float4(acc[i][0], acc[i][1], acc[i][2], acc[i][3]);
        float4 c1 = make_float4(acc[i][4], acc[i][5], acc[i][6], acc[i][7]);
        *(float4*)&C[(size_t)(bm + tr + i) * N + bn + tc] = c0;
        *(float4*)&C[(size_t)(bm + tr + i) * N + bn + tc + 4] = c1;
    }
}

// ============================================================================
// RoPE on K and V (interleaved pair convention per reference).
// K/V: [S, 8, 64] flattened to [S, 512]. cos/sin: [S, 32].
// One thread per (s, kv_head, pair) handles both K and V.
// total threads = 2048 * 8 * 32 = 524288
// ============================================================================
__global__ __launch_bounds__(256) void rope_kernel(
    float* __restrict__ K, float* __restrict__ V,
    const float* __restrict__ cs, const float* __restrict__ sn)
{
    int idx = blockIdx.x * 256 + threadIdx.x;
    int s = idx >> 8;          // / 256
    int r = idx & 255;
    int h = r >> 5;            // kv head 0..7
    int i = r & 31;            // pair 0..31
    float c = cs[s * 32 + i];
    float si = sn[s * 32 + i];
    int base = s * NKV_D + h * HD + 2 * i;

    float k0 = K[base], k1 = K[base + 1];
    K[base]     = k0 * c - k1 * si;
    K[base + 1] = k0 * si + k1 * c;

    float v0 = V[base], v1 = V[base + 1];
    V[base]     = v0 * c - v1 * si;
    V[base + 1] = v0 * si + v1 * c;
}

// ============================================================================
// Causal flash attention, fp32.
// grid (16, 32): (query block of 128, head). 128 threads, 1 query per thread.
// KV tiles of 32 rows staged in smem; scores staged in Ss[j][tid] (conflict-free).
// Q,Y: [S, 2048] head-major columns. K,V: [S, 512].
// ============================================================================
__global__ __launch_bounds__(128) void attn_kernel(
    const float* __restrict__ Q, const float* __restrict__ Kb,
    const float* __restrict__ Vb, float* __restrict__ Y)
{
    __shared__ float Ks[32][64];
    __shared__ float Vs[32][64];
    __shared__ float Ss[32][128];   // scores [j][tid] — tid-contiguous, no conflicts

    const int br = 15 - blockIdx.x;      // heavy blocks first (load balance)
    const int h = blockIdx.y;
    const int tid = threadIdx.x;
    const int qi = br * 128 + tid;
    const int kvh = h >> 2;

    float q[64];
    const float* qp = &Q[(size_t)qi * DMODEL + h * HD];
#pragma unroll
    for (int d = 0; d < 64; d += 4)
        *(float4*)&q[d] = *(const float4*)&qp[d];

    float acc[64];
#pragma unroll
    for (int d = 0; d < 64; d++) acc[d] = 0.f;
    float m = -1e30f, l = 0.f;

    const int ntiles = 4 * (br + 1);     // cover KV rows [0, br*128+128)
    for (int t = 0; t < ntiles; t++) {
        const int kb = t * 32;
        // cooperative load of K/V tiles: 32x64 floats each = 512 float4; 4/thread
#pragma unroll
        for (int i = 0; i < 4; i++) {
            int id = tid + i * 128;
            int row = id >> 4;
            int col = (id & 15) * 4;
            size_t goff = (size_t)(kb + row) * NKV_D + kvh * HD + col;
            *(float4*)&Ks[row][col] = *(const float4*)&Kb[goff];
            *(float4*)&Vs[row][col] = *(const float4*)&Vb[goff];
        }
        __syncthreads();

        float tmax = -1e30f;
#pragma unroll
        for (int j = 0; j < 32; j++) {
            float s = 0.f;
#pragma unroll
            for (int d = 0; d < 64; d += 4) {
                float4 kv = *(float4*)&Ks[j][d];
                s += q[d] * kv.x + q[d + 1] * kv.y
                   + q[d + 2] * kv.z + q[d + 3] * kv.w;
            }
            s *= 0.125f;                       // hd^-0.5
            if (kb + j > qi) s = -1e30f;       // causal
            Ss[j][tid] = s;
            tmax = fmaxf(tmax, s);
        }

        float mnew = fmaxf(m, tmax);
        float corr = __expf(m - mnew);
        l *= corr;
#pragma unroll
        for (int d = 0; d < 64; d++) acc[d] *= corr;

#pragma unroll
        for (int j = 0; j < 32; j++) {
            float p = __expf(Ss[j][tid] - mnew);
            l += p;
#pragma unroll
            for (int d = 0; d < 64; d += 4) {
                float4 vv = *(float4*)&Vs[j][d];
                acc[d]     += p * vv.x;
                acc[d + 1] += p * vv.y;
                acc[d + 2] += p * vv.z;
                acc[d + 3] += p * vv.w;
            }
        }
        m = mnew;
        __syncthreads();
    }

    float inv = 1.f / l;
    float* yp = &Y[(size_t)qi * DMODEL + h * HD];
#pragma unroll
    for (int d = 0; d < 64; d += 4) {
        float4 o = make_float4(acc[d] * inv, acc[d + 1] * inv,
                               acc[d + 2] * inv, acc[d + 3] * inv);
        *(float4*)&yp[d] = o;
    }
}

// ============================================================================
// Launch
// ============================================================================
extern "C" void kernel_launch(void* const* d_in, const int* in_sizes, int n_in,
                              void* d_out, int out_size)
{
    const float* x    = (const float*)d_in[0];
    const float* tcos = (const float*)d_in[1];
    const float* tsin = (const float*)d_in[2];
    const float* wq   = (const float*)d_in[3];
    const float* wk   = (const float*)d_in[4];
    const float* wv   = (const float*)d_in[5];
    const float* wo   = (const float*)d_in[6];
    float* out = (float*)d_out;

    float *Q, *K, *V, *Y;
    cudaGetSymbolAddress((void**)&Q, g_Q);
    cudaGetSymbolAddress((void**)&K, g_K);
    cudaGetSymbolAddress((void**)&V, g_V);
    cudaGetSymbolAddress((void**)&Y, g_Y);

    dim3 gbig(DMODEL / GBN, S_LEN / GBM);   // (16,16)
    dim3 gkv(NKV_D / GBN, S_LEN / GBM);     // (4,16)

    gemm_kernel<<<gbig, 256>>>(x, wq, Q, S_LEN, DMODEL, DMODEL);
    gemm_kernel<<<gkv, 256>>>(x, wk, K, S_LEN, NKV_D, DMODEL);
    gemm_kernel<<<gkv, 256>>>(x, wv, V, S_LEN, NKV_D, DMODEL);

    rope_kernel<<<(S_LEN * 256) / 256, 256>>>(K, V, tcos, tsin);

    attn_kernel<<<dim3(16, NHEADS), 128>>>(Q, K, V, Y);

    gemm_kernel<<<gbig, 256>>>(Y, wo, out, S_LEN, DMODEL, DMODEL);
}

// round 7
// speedup vs baseline: 1.3809x; 1.3809x over previous
#include <cuda_runtime.h>
#include <cuda_bf16.h>
#include <math.h>
#include <cstdint>

// Problem constants: B=1, S=2048, D=2048, 32 heads, hd=64, 8 KV heads (GQA rep=4)
#define S_LEN 2048
#define DMODEL 2048
#define NKV_D 512
#define HD 64
#define NHEADS 32

// -------- scratch (no allocations allowed; device globals) --------
__device__ float g_Q[S_LEN * DMODEL];   // 16 MB
__device__ float g_K[S_LEN * NKV_D];    // 4 MB
__device__ float g_V[S_LEN * NKV_D];    // 4 MB
__device__ float g_Y[S_LEN * DMODEL];   // 16 MB

// ============================================================================
// Warp-MMA primitives (base sm_103 ISA: ldmatrix + mma.sync -> HMMA).
// NOTE: tcgen05/TMA are compute_103a-only at the PTX level; this harness
// builds PTX at compute_103, so those are unavailable. mma.sync is the
// fastest reachable tensor path.
// ============================================================================
__device__ __forceinline__ uint32_t smem_u32(const void* p) {
    uint32_t a;
    asm("{ .reg .u64 t; cvta.to.shared.u64 t, %1; cvt.u32.u64 %0, t; }"
        : "=r"(a) : "l"(p));
    return a;
}
__device__ __forceinline__ void ldmx4(uint32_t* r, uint32_t a) {
    asm volatile("ldmatrix.sync.aligned.m8n8.x4.shared.b16 {%0,%1,%2,%3}, [%4];"
        : "=r"(r[0]), "=r"(r[1]), "=r"(r[2]), "=r"(r[3]) : "r"(a));
}
__device__ __forceinline__ void ldmx2(uint32_t* r, uint32_t a) {
    asm volatile("ldmatrix.sync.aligned.m8n8.x2.shared.b16 {%0,%1}, [%2];"
        : "=r"(r[0]), "=r"(r[1]) : "r"(a));
}
__device__ __forceinline__ void mma16816(float* d, const uint32_t* a, const uint32_t* b) {
    asm volatile("mma.sync.aligned.m16n8k16.row.col.f32.bf16.bf16.f32 "
                 "{%0,%1,%2,%3}, {%4,%5,%6,%7}, {%8,%9}, {%0,%1,%2,%3};"
                 : "+f"(d[0]), "+f"(d[1]), "+f"(d[2]), "+f"(d[3])
                 : "r"(a[0]), "r"(a[1]), "r"(a[2]), "r"(a[3]),
                   "r"(b[0]), "r"(b[1]));
}

// ---- split-bf16 helpers ----
__device__ __forceinline__ uint32_t pack2(__nv_bfloat16 a, __nv_bfloat16 b) {
    return (uint32_t)__bfloat16_as_ushort(a) | ((uint32_t)__bfloat16_as_ushort(b) << 16);
}
__device__ __forceinline__ void split4(float x0, float x1, float x2, float x3,
                                       uint2& hi, uint2& lo) {
    __nv_bfloat16 h0 = __float2bfloat16_rn(x0);
    __nv_bfloat16 h1 = __float2bfloat16_rn(x1);
    __nv_bfloat16 h2 = __float2bfloat16_rn(x2);
    __nv_bfloat16 h3 = __float2bfloat16_rn(x3);
    float l0 = x0 - __bfloat162float(h0);
    float l1 = x1 - __bfloat162float(h1);
    float l2 = x2 - __bfloat162float(h2);
    float l3 = x3 - __bfloat162float(h3);
    hi.x = pack2(h0, h1);
    hi.y = pack2(h2, h3);
    lo.x = pack2(__float2bfloat16_rn(l0), __float2bfloat16_rn(l1));
    lo.y = pack2(__float2bfloat16_rn(l2), __float2bfloat16_rn(l3));
}

// ============================================================================
// Split-bf16 GEMM via mma.sync: C[M,N] = A[M,K] @ B[K,N], fp32 I/O.
// CTA tile 128x128, BK=32 (bf16), 256 threads = 8 warps in 4(m) x 2(n).
// Warp tile 32x64 = 2 x 8 m16n8k16 mma tiles, 3 passes (AhBh + AhBl + AlBh).
// Double-buffered smem; register-staged fp32 loads with hi/lo split.
// smem layout per stage: [Ahi | Alo | Bhi | Blo], each 128 rows x 80 B
// (64 B data = 32 bf16 + 16 B pad; pad makes ldmatrix conflict-free).
// ============================================================================
#define BKk 32
#define ROWB 80
#define TILEB (128 * ROWB)      // 10240 B
#define STGB  (4 * TILEB)       // 40960 B
#define GSMEM (2 * STGB)        // 81920 B

__global__ __launch_bounds__(256) void gemm_mma(
    const float* __restrict__ A, const float* __restrict__ B,
    float* __restrict__ C, int M, int N, int K)
{
    extern __shared__ char smem[];
    const int tid = threadIdx.x;
    const int w = tid >> 5;
    const int lane = tid & 31;
    const int wm = (w & 3) * 32;
    const int wn = (w >> 2) * 64;
    const int bm = blockIdx.y * 128;
    const int bn = blockIdx.x * 128;
    const uint32_t sb = smem_u32(smem);

    float acc[2][8][4];
#pragma unroll
    for (int mi = 0; mi < 2; mi++)
#pragma unroll
        for (int ni = 0; ni < 8; ni++)
#pragma unroll
            for (int v = 0; v < 4; v++) acc[mi][ni][v] = 0.f;

    // staging registers for the next K-stage
    float4 aS[4];
    float  bS[4][4];

    // thread's fixed staging coordinates
    const int arow[4] = { (tid + 0) >> 3, (tid + 256) >> 3, (tid + 512) >> 3, (tid + 768) >> 3 };
    const int akc = (tid & 7) * 4;                 // same for all i (id&7 == tid&7)
    const int bn_i = tid & 127;                    // same for all i
    const int bkg[4] = { (tid + 0) >> 7, (tid + 256) >> 7, (tid + 512) >> 7, (tid + 768) >> 7 };

    const int NT = K / BKk;

#define LOADG(kt)                                                              \
    {                                                                          \
        _Pragma("unroll")                                                      \
        for (int i = 0; i < 4; i++)                                            \
            aS[i] = *(const float4*)&A[(size_t)(bm + arow[i]) * K + (kt) * BKk + akc]; \
        _Pragma("unroll")                                                      \
        for (int i = 0; i < 4; i++) {                                          \
            const float* bp = &B[(size_t)((kt) * BKk + bkg[i] * 4) * N + bn + bn_i]; \
            bS[i][0] = bp[0];                                                  \
            bS[i][1] = bp[N];                                                  \
            bS[i][2] = bp[2 * (size_t)N];                                      \
            bS[i][3] = bp[3 * (size_t)N];                                      \
        }                                                                      \
    }

#define STORES(buf)                                                            \
    {                                                                          \
        char* st = smem + (buf) * STGB;                                        \
        _Pragma("unroll")                                                      \
        for (int i = 0; i < 4; i++) {                                          \
            uint2 hi, lo;                                                      \
            split4(aS[i].x, aS[i].y, aS[i].z, aS[i].w, hi, lo);                \
            uint32_t off = (uint32_t)(arow[i] * ROWB + akc * 2);               \
            *(uint2*)(st + off)         = hi;                                  \
            *(uint2*)(st + TILEB + off) = lo;                                  \
        }                                                                      \
        _Pragma("unroll")                                                      \
        for (int i = 0; i < 4; i++) {                                          \
            uint2 hi, lo;                                                      \
            split4(bS[i][0], bS[i][1], bS[i][2], bS[i][3], hi, lo);            \
            uint32_t off = (uint32_t)(bn_i * ROWB + bkg[i] * 8);               \
            *(uint2*)(st + 2 * TILEB + off) = hi;                              \
            *(uint2*)(st + 3 * TILEB + off) = lo;                              \
        }                                                                      \
    }

    // prologue: stage 0
    LOADG(0);
    STORES(0);
    __syncthreads();

    for (int kt = 0; kt < NT; kt++) {
        const int buf = kt & 1;
        if (kt + 1 < NT) LOADG(kt + 1);

        const uint32_t sbase = sb + buf * STGB;
#pragma unroll
        for (int ks = 0; ks < BKk; ks += 16) {
            uint32_t ah[2][4], al[2][4], bh[8][2], bl[8][2];
#pragma unroll
            for (int mi = 0; mi < 2; mi++) {
                uint32_t addr = sbase
                    + (uint32_t)((wm + mi * 16 + (lane & 15)) * ROWB)
                    + (uint32_t)(ks * 2 + (lane >> 4) * 16);
                ldmx4(ah[mi], addr);
                ldmx4(al[mi], addr + TILEB);
            }
#pragma unroll
            for (int ni = 0; ni < 8; ni++) {
                uint32_t addr = sbase + 2 * TILEB
                    + (uint32_t)((wn + ni * 8 + (lane & 7)) * ROWB)
                    + (uint32_t)(ks * 2 + ((lane >> 3) & 1) * 16);
                ldmx2(bh[ni], addr);
                ldmx2(bl[ni], addr + TILEB);
            }
#pragma unroll
            for (int mi = 0; mi < 2; mi++)
#pragma unroll
                for (int ni = 0; ni < 8; ni++) {
                    mma16816(acc[mi][ni], ah[mi], bh[ni]);
                    mma16816(acc[mi][ni], ah[mi], bl[ni]);
                    mma16816(acc[mi][ni], al[mi], bh[ni]);
                }
        }

        if (kt + 1 < NT) {
            STORES(buf ^ 1);
            __syncthreads();
        }
    }

    // epilogue: c0,c1 -> (row, col..col+1); c2,c3 -> (row+8, ...)
    const int er = lane >> 2;
    const int ec = (lane & 3) * 2;
#pragma unroll
    for (int mi = 0; mi < 2; mi++)
#pragma unroll
        for (int ni = 0; ni < 8; ni++) {
            int r0 = bm + wm + mi * 16 + er;
            int c0 = bn + wn + ni * 8 + ec;
            *(float2*)&C[(size_t)r0 * N + c0] =
                make_float2(acc[mi][ni][0], acc[mi][ni][1]);
            *(float2*)&C[(size_t)(r0 + 8) * N + c0] =
                make_float2(acc[mi][ni][2], acc[mi][ni][3]);
        }
#undef LOADG
#undef STORES
}

// ============================================================================
// RoPE on K and V (interleaved pairs). K/V: [S, 512]. cos/sin: [S, 32].
// ============================================================================
__global__ __launch_bounds__(256) void rope_kernel(
    float* __restrict__ K, float* __restrict__ V,
    const float* __restrict__ cs, const float* __restrict__ sn)
{
    int idx = blockIdx.x * 256 + threadIdx.x;
    int s = idx >> 8;
    int r = idx & 255;
    int h = r >> 5;
    int i = r & 31;
    float c = cs[s * 32 + i];
    float si = sn[s * 32 + i];
    int base = s * NKV_D + h * HD + 2 * i;

    float k0 = K[base], k1 = K[base + 1];
    K[base]     = k0 * c - k1 * si;
    K[base + 1] = k0 * si + k1 * c;

    float v0 = V[base], v1 = V[base + 1];
    V[base]     = v0 * c - v1 * si;
    V[base + 1] = v0 * si + v1 * c;
}

// ============================================================================
// Causal flash attention, fp32 (unchanged this round).
// grid (16, 32): (query block of 128, head). 128 threads, 1 query per thread.
// ============================================================================
__global__ __launch_bounds__(128) void attn_kernel(
    const float* __restrict__ Q, const float* __restrict__ Kb,
    const float* __restrict__ Vb, float* __restrict__ Y)
{
    __shared__ float Ks[32][64];
    __shared__ float Vs[32][64];
    __shared__ float Ss[32][128];

    const int br = 15 - blockIdx.x;
    const int h = blockIdx.y;
    const int tid = threadIdx.x;
    const int qi = br * 128 + tid;
    const int kvh = h >> 2;

    float q[64];
    const float* qp = &Q[(size_t)qi * DMODEL + h * HD];
#pragma unroll
    for (int d = 0; d < 64; d += 4)
        *(float4*)&q[d] = *(const float4*)&qp[d];

    float acc[64];
#pragma unroll
    for (int d = 0; d < 64; d++) acc[d] = 0.f;
    float m = -1e30f, l = 0.f;

    const int ntiles = 4 * (br + 1);
    for (int t = 0; t < ntiles; t++) {
        const int kb = t * 32;
#pragma unroll
        for (int i = 0; i < 4; i++) {
            int id = tid + i * 128;
            int row = id >> 4;
            int col = (id & 15) * 4;
            size_t goff = (size_t)(kb + row) * NKV_D + kvh * HD + col;
            *(float4*)&Ks[row][col] = *(const float4*)&Kb[goff];
            *(float4*)&Vs[row][col] = *(const float4*)&Vb[goff];
        }
        __syncthreads();

        float tmax = -1e30f;
#pragma unroll
        for (int j = 0; j < 32; j++) {
            float s = 0.f;
#pragma unroll
            for (int d = 0; d < 64; d += 4) {
                float4 kv = *(float4*)&Ks[j][d];
                s += q[d] * kv.x + q[d + 1] * kv.y
                   + q[d + 2] * kv.z + q[d + 3] * kv.w;
            }
            s *= 0.125f;
            if (kb + j > qi) s = -1e30f;
            Ss[j][tid] = s;
            tmax = fmaxf(tmax, s);
        }

        float mnew = fmaxf(m, tmax);
        float corr = __expf(m - mnew);
        l *= corr;
#pragma unroll
        for (int d = 0; d < 64; d++) acc[d] *= corr;

#pragma unroll
        for (int j = 0; j < 32; j++) {
            float p = __expf(Ss[j][tid] - mnew);
            l += p;
#pragma unroll
            for (int d = 0; d < 64; d += 4) {
                float4 vv = *(float4*)&Vs[j][d];
                acc[d]     += p * vv.x;
                acc[d + 1] += p * vv.y;
                acc[d + 2] += p * vv.z;
                acc[d + 3] += p * vv.w;
            }
        }
        m = mnew;
        __syncthreads();
    }

    float inv = 1.f / l;
    float* yp = &Y[(size_t)qi * DMODEL + h * HD];
#pragma unroll
    for (int d = 0; d < 64; d += 4) {
        float4 o = make_float4(acc[d] * inv, acc[d + 1] * inv,
                               acc[d + 2] * inv, acc[d + 3] * inv);
        *(float4*)&yp[d] = o;
    }
}

// ============================================================================
// Launch
// ============================================================================
extern "C" void kernel_launch(void* const* d_in, const int* in_sizes, int n_in,
                              void* d_out, int out_size)
{
    const float* x    = (const float*)d_in[0];
    const float* tcos = (const float*)d_in[1];
    const float* tsin = (const float*)d_in[2];
    const float* wq   = (const float*)d_in[3];
    const float* wk   = (const float*)d_in[4];
    const float* wv   = (const float*)d_in[5];
    const float* wo   = (const float*)d_in[6];
    float* out = (float*)d_out;

    float *Q, *K, *V, *Y;
    cudaGetSymbolAddress((void**)&Q, g_Q);
    cudaGetSymbolAddress((void**)&K, g_K);
    cudaGetSymbolAddress((void**)&V, g_V);
    cudaGetSymbolAddress((void**)&Y, g_Y);

    // idempotent; called every time (no static guards allowed)
    cudaFuncSetAttribute(gemm_mma, cudaFuncAttributeMaxDynamicSharedMemorySize, GSMEM);

    dim3 gbig(DMODEL / 128, S_LEN / 128);   // (16,16)
    dim3 gkv(NKV_D / 128, S_LEN / 128);     // (4,16)

    gemm_mma<<<gbig, 256, GSMEM>>>(x, wq, Q, S_LEN, DMODEL, DMODEL);
    gemm_mma<<<gkv, 256, GSMEM>>>(x, wk, K, S_LEN, NKV_D, DMODEL);
    gemm_mma<<<gkv, 256, GSMEM>>>(x, wv, V, S_LEN, NKV_D, DMODEL);

    rope_kernel<<<(S_LEN * 256) / 256, 256>>>(K, V, tcos, tsin);

    attn_kernel<<<dim3(16, NHEADS), 128>>>(Q, K, V, Y);

    gemm_mma<<<gbig, 256, GSMEM>>>(Y, wo, out, S_LEN, DMODEL, DMODEL);
}

// round 11
// speedup vs baseline: 1.7982x; 1.3022x over previous
#include <cuda_runtime.h>
#include <cuda_bf16.h>
#include <math.h>
#include <cstdint>

// Problem constants: B=1, S=2048, D=2048, 32 heads, hd=64, 8 KV heads (GQA rep=4)
#define S_LEN 2048
#define DMODEL 2048
#define NKV_D 512
#define HD 64
#define NHEADS 32

// -------- scratch (no allocations allowed; device globals) --------
__device__ float g_Q[S_LEN * DMODEL];   // 16 MB
__device__ float g_K[S_LEN * NKV_D];    // 4 MB (fp32, pre-rope)
__device__ float g_V[S_LEN * NKV_D];    // 4 MB
__device__ float g_Y[S_LEN * DMODEL];   // 16 MB
__device__ __nv_bfloat16 g_Kh[S_LEN * NKV_D];  // 2 MB each: rope'd hi/lo splits
__device__ __nv_bfloat16 g_Kl[S_LEN * NKV_D];
__device__ __nv_bfloat16 g_Vh[S_LEN * NKV_D];
__device__ __nv_bfloat16 g_Vl[S_LEN * NKV_D];

// ============================================================================
// Warp-MMA primitives (base sm_103 ISA: ldmatrix + mma.sync -> HMMA).
// tcgen05/TMA are compute_103a-only at the PTX level; harness builds
// compute_103, so mma.sync is the fastest reachable tensor path.
// ============================================================================
__device__ __forceinline__ uint32_t smem_u32(const void* p) {
    uint32_t a;
    asm("{ .reg .u64 t; cvta.to.shared.u64 t, %1; cvt.u32.u64 %0, t; }"
        : "=r"(a) : "l"(p));
    return a;
}
__device__ __forceinline__ void ldmx4(uint32_t* r, uint32_t a) {
    asm volatile("ldmatrix.sync.aligned.m8n8.x4.shared.b16 {%0,%1,%2,%3}, [%4];"
        : "=r"(r[0]), "=r"(r[1]), "=r"(r[2]), "=r"(r[3]) : "r"(a));
}
__device__ __forceinline__ void ldmx4t(uint32_t* r, uint32_t a) {
    asm volatile("ldmatrix.sync.aligned.m8n8.x4.trans.shared.b16 {%0,%1,%2,%3}, [%4];"
        : "=r"(r[0]), "=r"(r[1]), "=r"(r[2]), "=r"(r[3]) : "r"(a));
}
__device__ __forceinline__ void ldmx2(uint32_t* r, uint32_t a) {
    asm volatile("ldmatrix.sync.aligned.m8n8.x2.shared.b16 {%0,%1}, [%2];"
        : "=r"(r[0]), "=r"(r[1]) : "r"(a));
}
__device__ __forceinline__ void mma16816(float* d, const uint32_t* a, const uint32_t* b) {
    asm volatile("mma.sync.aligned.m16n8k16.row.col.f32.bf16.bf16.f32 "
                 "{%0,%1,%2,%3}, {%4,%5,%6,%7}, {%8,%9}, {%0,%1,%2,%3};"
                 : "+f"(d[0]), "+f"(d[1]), "+f"(d[2]), "+f"(d[3])
                 : "r"(a[0]), "r"(a[1]), "r"(a[2]), "r"(a[3]),
                   "r"(b[0]), "r"(b[1]));
}

// ---- split-bf16 helpers ----
__device__ __forceinline__ uint32_t pack2(__nv_bfloat16 a, __nv_bfloat16 b) {
    return (uint32_t)__bfloat16_as_ushort(a) | ((uint32_t)__bfloat16_as_ushort(b) << 16);
}
__device__ __forceinline__ void split4(float x0, float x1, float x2, float x3,
                                       uint2& hi, uint2& lo) {
    __nv_bfloat16 h0 = __float2bfloat16_rn(x0);
    __nv_bfloat16 h1 = __float2bfloat16_rn(x1);
    __nv_bfloat16 h2 = __float2bfloat16_rn(x2);
    __nv_bfloat16 h3 = __float2bfloat16_rn(x3);
    float l0 = x0 - __bfloat162float(h0);
    float l1 = x1 - __bfloat162float(h1);
    float l2 = x2 - __bfloat162float(h2);
    float l3 = x3 - __bfloat162float(h3);
    hi.x = pack2(h0, h1);
    hi.y = pack2(h2, h3);
    lo.x = pack2(__float2bfloat16_rn(l0), __float2bfloat16_rn(l1));
    lo.y = pack2(__float2bfloat16_rn(l2), __float2bfloat16_rn(l3));
}

// ============================================================================
// Split-bf16 GEMM via mma.sync (unchanged from R7 — passing).
// CTA 128x128, BK=32, 256 threads = 8 warps (4m x 2n), warp 32x64.
// ============================================================================
#define BKk 32
#define ROWB 80
#define TILEB (128 * ROWB)
#define STGB  (4 * TILEB)
#define GSMEM (2 * STGB)

__global__ __launch_bounds__(256) void gemm_mma(
    const float* __restrict__ A, const float* __restrict__ B,
    float* __restrict__ C, int M, int N, int K)
{
    extern __shared__ char smem[];
    const int tid = threadIdx.x;
    const int w = tid >> 5;
    const int lane = tid & 31;
    const int wm = (w & 3) * 32;
    const int wn = (w >> 2) * 64;
    const int bm = blockIdx.y * 128;
    const int bn = blockIdx.x * 128;
    const uint32_t sb = smem_u32(smem);

    float acc[2][8][4];
#pragma unroll
    for (int mi = 0; mi < 2; mi++)
#pragma unroll
        for (int ni = 0; ni < 8; ni++)
#pragma unroll
            for (int v = 0; v < 4; v++) acc[mi][ni][v] = 0.f;

    float4 aS[4];
    float  bS[4][4];

    const int arow[4] = { (tid + 0) >> 3, (tid + 256) >> 3, (tid + 512) >> 3, (tid + 768) >> 3 };
    const int akc = (tid & 7) * 4;
    const int bn_i = tid & 127;
    const int bkg[4] = { (tid + 0) >> 7, (tid + 256) >> 7, (tid + 512) >> 7, (tid + 768) >> 7 };

    const int NT = K / BKk;

#define LOADG(kt)                                                              \
    {                                                                          \
        _Pragma("unroll")                                                      \
        for (int i = 0; i < 4; i++)                                            \
            aS[i] = *(const float4*)&A[(size_t)(bm + arow[i]) * K + (kt) * BKk + akc]; \
        _Pragma("unroll")                                                      \
        for (int i = 0; i < 4; i++) {                                          \
            const float* bp = &B[(size_t)((kt) * BKk + bkg[i] * 4) * N + bn + bn_i]; \
            bS[i][0] = bp[0];                                                  \
            bS[i][1] = bp[N];                                                  \
            bS[i][2] = bp[2 * (size_t)N];                                      \
            bS[i][3] = bp[3 * (size_t)N];                                      \
        }                                                                      \
    }

#define STORES(buf)                                                            \
    {                                                                          \
        char* st = smem + (buf) * STGB;                                        \
        _Pragma("unroll")                                                      \
        for (int i = 0; i < 4; i++) {                                          \
            uint2 hi, lo;                                                      \
            split4(aS[i].x, aS[i].y, aS[i].z, aS[i].w, hi, lo);                \
            uint32_t off = (uint32_t)(arow[i] * ROWB + akc * 2);               \
            *(uint2*)(st + off)         = hi;                                  \
            *(uint2*)(st + TILEB + off) = lo;                                  \
        }                                                                      \
        _Pragma("unroll")                                                      \
        for (int i = 0; i < 4; i++) {                                          \
            uint2 hi, lo;                                                      \
            split4(bS[i][0], bS[i][1], bS[i][2], bS[i][3], hi, lo);            \
            uint32_t off = (uint32_t)(bn_i * ROWB + bkg[i] * 8);               \
            *(uint2*)(st + 2 * TILEB + off) = hi;                              \
            *(uint2*)(st + 3 * TILEB + off) = lo;                              \
        }                                                                      \
    }

    LOADG(0);
    STORES(0);
    __syncthreads();

    for (int kt = 0; kt < NT; kt++) {
        const int buf = kt & 1;
        if (kt + 1 < NT) LOADG(kt + 1);

        const uint32_t sbase = sb + buf * STGB;
#pragma unroll
        for (int ks = 0; ks < BKk; ks += 16) {
            uint32_t ah[2][4], al[2][4], bh[8][2], bl[8][2];
#pragma unroll
            for (int mi = 0; mi < 2; mi++) {
                uint32_t addr = sbase
                    + (uint32_t)((wm + mi * 16 + (lane & 15)) * ROWB)
                    + (uint32_t)(ks * 2 + (lane >> 4) * 16);
                ldmx4(ah[mi], addr);
                ldmx4(al[mi], addr + TILEB);
            }
#pragma unroll
            for (int ni = 0; ni < 8; ni++) {
                uint32_t addr = sbase + 2 * TILEB
                    + (uint32_t)((wn + ni * 8 + (lane & 7)) * ROWB)
                    + (uint32_t)(ks * 2 + ((lane >> 3) & 1) * 16);
                ldmx2(bh[ni], addr);
                ldmx2(bl[ni], addr + TILEB);
            }
#pragma unroll
            for (int mi = 0; mi < 2; mi++)
#pragma unroll
                for (int ni = 0; ni < 8; ni++) {
                    mma16816(acc[mi][ni], ah[mi], bh[ni]);
                    mma16816(acc[mi][ni], ah[mi], bl[ni]);
                    mma16816(acc[mi][ni], al[mi], bh[ni]);
                }
        }

        if (kt + 1 < NT) {
            STORES(buf ^ 1);
            __syncthreads();
        }
    }

    const int er = lane >> 2;
    const int ec = (lane & 3) * 2;
#pragma unroll
    for (int mi = 0; mi < 2; mi++)
#pragma unroll
        for (int ni = 0; ni < 8; ni++) {
            int r0 = bm + wm + mi * 16 + er;
            int c0 = bn + wn + ni * 8 + ec;
            *(float2*)&C[(size_t)r0 * N + c0] =
                make_float2(acc[mi][ni][0], acc[mi][ni][1]);
            *(float2*)&C[(size_t)(r0 + 8) * N + c0] =
                make_float2(acc[mi][ni][2], acc[mi][ni][3]);
        }
#undef LOADG
#undef STORES
}

// ============================================================================
// RoPE on K and V + split to bf16 hi/lo globals (consumed by attn_mma).
// K/V fp32: [S, 512]. cos/sin: [S, 32]. One thread per (s, kv head, pair).
// ============================================================================
__global__ __launch_bounds__(256) void rope_split_kernel(
    const float* __restrict__ K, const float* __restrict__ V,
    const float* __restrict__ cs, const float* __restrict__ sn,
    __nv_bfloat16* __restrict__ Kh, __nv_bfloat16* __restrict__ Kl,
    __nv_bfloat16* __restrict__ Vh, __nv_bfloat16* __restrict__ Vl)
{
    int idx = blockIdx.x * 256 + threadIdx.x;
    int s = idx >> 8;
    int r = idx & 255;
    int h = r >> 5;
    int i = r & 31;
    float c = cs[s * 32 + i];
    float si = sn[s * 32 + i];
    int base = s * NKV_D + h * HD + 2 * i;

    float k0 = K[base], k1 = K[base + 1];
    float rk0 = k0 * c - k1 * si;
    float rk1 = k0 * si + k1 * c;
    float v0 = V[base], v1 = V[base + 1];
    float rv0 = v0 * c - v1 * si;
    float rv1 = v0 * si + v1 * c;

    __nv_bfloat16 h0 = __float2bfloat16_rn(rk0);
    __nv_bfloat16 h1 = __float2bfloat16_rn(rk1);
    Kh[base]     = h0;
    Kh[base + 1] = h1;
    Kl[base]     = __float2bfloat16_rn(rk0 - __bfloat162float(h0));
    Kl[base + 1] = __float2bfloat16_rn(rk1 - __bfloat162float(h1));

    h0 = __float2bfloat16_rn(rv0);
    h1 = __float2bfloat16_rn(rv1);
    Vh[base]     = h0;
    Vh[base + 1] = h1;
    Vl[base]     = __float2bfloat16_rn(rv0 - __bfloat162float(h0));
    Vl[base + 1] = __float2bfloat16_rn(rv1 - __bfloat162float(h1));
}

// ============================================================================
// Causal flash attention via mma.sync, split-bf16 3-pass on QK^T and PV.
// grid (32, 32) = (q block of 64, head). 128 threads = 4 warps x 16 q rows.
// kv tiles of 64; BM=BN=64 so only the last tile needs the causal mask.
// smem: 6 tiles [64 rows x 144 B pitch]: Qh Ql Kh Kl Vh Vl = 54 KB.
// ============================================================================
#define AROW 144
#define ATILE (64 * AROW)     // 9216 B
#define ASMEM (6 * ATILE)     // 55296 B

__global__ __launch_bounds__(128) void attn_mma(
    const float* __restrict__ Qf,
    const __nv_bfloat16* __restrict__ Khg, const __nv_bfloat16* __restrict__ Klg,
    const __nv_bfloat16* __restrict__ Vhg, const __nv_bfloat16* __restrict__ Vlg,
    float* __restrict__ Y)
{
    extern __shared__ char sm[];
    const uint32_t sb = smem_u32(sm);
    const int tid = threadIdx.x;
    const int w = tid >> 5;
    const int lane = tid & 31;
    const int qb = 31 - (int)blockIdx.x;     // heavy blocks first
    const int h = blockIdx.y;
    const int kvh = h >> 2;
    const int wm = w * 16;

    // ---- load + split Q tile [64 q rows][64 hd] ----
#pragma unroll
    for (int i = 0; i < 8; i++) {
        int id = tid + i * 128;
        int row = id >> 4;
        int c4 = (id & 15) * 4;
        float4 v = *(const float4*)&Qf[(size_t)(qb * 64 + row) * DMODEL + h * HD + c4];
        uint2 hi, lo;
        split4(v.x, v.y, v.z, v.w, hi, lo);
        *(uint2*)(sm + row * AROW + c4 * 2)         = hi;
        *(uint2*)(sm + ATILE + row * AROW + c4 * 2) = lo;
    }
    __syncthreads();

    // ---- Q fragments (kept in registers) ----
    uint32_t qh[4][4], ql[4][4];
#pragma unroll
    for (int kk = 0; kk < 4; kk++) {
        uint32_t addr = sb + (uint32_t)((wm + (lane & 15)) * AROW + kk * 32 + (lane >> 4) * 16);
        ldmx4(qh[kk], addr);
        ldmx4(ql[kk], addr + ATILE);
    }

    float o[8][4];
#pragma unroll
    for (int nt = 0; nt < 8; nt++)
#pragma unroll
        for (int v = 0; v < 4; v++) o[nt][v] = 0.f;
    float m0 = -1e30f, m1 = -1e30f, l0 = 0.f, l1 = 0.f;

    for (int t = 0; t <= qb; t++) {
        __syncthreads();    // previous tile's K/V reads complete
        const int kb = t * 64;
        // ---- cooperative K/V hi/lo tile load (bf16, already rope'd) ----
#pragma unroll
        for (int i = 0; i < 4; i++) {
            int id = tid + i * 128;
            int row = id >> 3;
            int ch = id & 7;
            size_t g = (size_t)(kb + row) * NKV_D + kvh * HD + ch * 8;
            uint32_t d = (uint32_t)(row * AROW + ch * 16);
            *(uint4*)(sm + 2 * ATILE + d) = *(const uint4*)&Khg[g];
            *(uint4*)(sm + 3 * ATILE + d) = *(const uint4*)&Klg[g];
            *(uint4*)(sm + 4 * ATILE + d) = *(const uint4*)&Vhg[g];
            *(uint4*)(sm + 5 * ATILE + d) = *(const uint4*)&Vlg[g];
        }
        __syncthreads();

        // ---- S = Q K^T (3-pass split) ----
        float s[8][4];
#pragma unroll
        for (int nt = 0; nt < 8; nt++)
#pragma unroll
            for (int v = 0; v < 4; v++) s[nt][v] = 0.f;

#pragma unroll
        for (int kk = 0; kk < 4; kk++) {
#pragma unroll
            for (int np = 0; np < 4; np++) {
                uint32_t ka = sb + 2 * ATILE
                    + (uint32_t)((np * 16 + (lane & 7) + (lane >> 4) * 8) * AROW
                                 + kk * 32 + ((lane >> 3) & 1) * 16);
                uint32_t kh4[4], kl4[4];
                ldmx4(kh4, ka);
                ldmx4(kl4, ka + ATILE);
                mma16816(s[2 * np],     qh[kk], kh4);
                mma16816(s[2 * np + 1], qh[kk], kh4 + 2);
                mma16816(s[2 * np],     qh[kk], kl4);
                mma16816(s[2 * np + 1], qh[kk], kl4 + 2);
                mma16816(s[2 * np],     ql[kk], kh4);
                mma16816(s[2 * np + 1], ql[kk], kh4 + 2);
            }
        }

        // ---- scale + causal mask (diagonal tile only) ----
        const int r0 = lane >> 2;
        const int c0b = 2 * (lane & 3);
        if (t == qb) {
#pragma unroll
            for (int nt = 0; nt < 8; nt++)
#pragma unroll
                for (int v = 0; v < 4; v++) {
                    int rr = wm + r0 + ((v >> 1) << 3);
                    int cc = nt * 8 + c0b + (v & 1);
                    s[nt][v] = (cc > rr) ? -1e30f : s[nt][v] * 0.125f;
                }
        } else {
#pragma unroll
            for (int nt = 0; nt < 8; nt++)
#pragma unroll
                for (int v = 0; v < 4; v++) s[nt][v] *= 0.125f;
        }

        // ---- online softmax (rows r0 and r0+8 per thread, 4-lane groups) ----
        float tm0 = -1e30f, tm1 = -1e30f;
#pragma unroll
        for (int nt = 0; nt < 8; nt++) {
            tm0 = fmaxf(tm0, fmaxf(s[nt][0], s[nt][1]));
            tm1 = fmaxf(tm1, fmaxf(s[nt][2], s[nt][3]));
        }
        tm0 = fmaxf(tm0, __shfl_xor_sync(0xffffffffu, tm0, 1));
        tm0 = fmaxf(tm0, __shfl_xor_sync(0xffffffffu, tm0, 2));
        tm1 = fmaxf(tm1, __shfl_xor_sync(0xffffffffu, tm1, 1));
        tm1 = fmaxf(tm1, __shfl_xor_sync(0xffffffffu, tm1, 2));

        float mn0 = fmaxf(m0, tm0), mn1 = fmaxf(m1, tm1);
        float sc0 = __expf(m0 - mn0), sc1 = __expf(m1 - mn1);
        m0 = mn0; m1 = mn1;

        float rs0 = 0.f, rs1 = 0.f;
#pragma unroll
        for (int nt = 0; nt < 8; nt++) {
            s[nt][0] = __expf(s[nt][0] - mn0);
            s[nt][1] = __expf(s[nt][1] - mn0);
            s[nt][2] = __expf(s[nt][2] - mn1);
            s[nt][3] = __expf(s[nt][3] - mn1);
            rs0 += s[nt][0] + s[nt][1];
            rs1 += s[nt][2] + s[nt][3];
        }
        rs0 += __shfl_xor_sync(0xffffffffu, rs0, 1);
        rs0 += __shfl_xor_sync(0xffffffffu, rs0, 2);
        rs1 += __shfl_xor_sync(0xffffffffu, rs1, 1);
        rs1 += __shfl_xor_sync(0xffffffffu, rs1, 2);
        l0 = l0 * sc0 + rs0;
        l1 = l1 * sc1 + rs1;

#pragma unroll
        for (int nt = 0; nt < 8; nt++) {
            o[nt][0] *= sc0; o[nt][1] *= sc0;
            o[nt][2] *= sc1; o[nt][3] *= sc1;
        }

        // ---- P fragments (hi/lo) directly from S acc (register identity) ----
        uint32_t ph[4][4], pl[4][4];
#pragma unroll
        for (int kk = 0; kk < 4; kk++) {
#pragma unroll
            for (int q2 = 0; q2 < 2; q2++) {
                int nt = 2 * kk + q2;
#pragma unroll
                for (int vv = 0; vv < 2; vv++) {
                    float p0f = s[nt][2 * vv], p1f = s[nt][2 * vv + 1];
                    __nv_bfloat16 b0 = __float2bfloat16_rn(p0f);
                    __nv_bfloat16 b1 = __float2bfloat16_rn(p1f);
                    ph[kk][2 * q2 + vv] = pack2(b0, b1);
                    pl[kk][2 * q2 + vv] =
                        pack2(__float2bfloat16_rn(p0f - __bfloat162float(b0)),
                              __float2bfloat16_rn(p1f - __bfloat162float(b1)));
                }
            }
        }

        // ---- O += P V (3-pass split), V fragments via ldmatrix.trans ----
#pragma unroll
        for (int kk = 0; kk < 4; kk++) {
#pragma unroll
            for (int np = 0; np < 4; np++) {
                uint32_t va = sb + 4 * ATILE
                    + (uint32_t)((kk * 16 + (lane & 15)) * AROW + np * 32 + (lane >> 4) * 16);
                uint32_t vh4[4], vl4[4];
                ldmx4t(vh4, va);
                ldmx4t(vl4, va + ATILE);
                mma16816(o[2 * np],     ph[kk], vh4);
                mma16816(o[2 * np + 1], ph[kk], vh4 + 2);
                mma16816(o[2 * np],     ph[kk], vl4);
                mma16816(o[2 * np + 1], ph[kk], vl4 + 2);
                mma16816(o[2 * np],     pl[kk], vh4);
                mma16816(o[2 * np + 1], pl[kk], vh4 + 2);
            }
        }
    }

    // ---- normalize + write ----
    float i0 = 1.f / l0, i1 = 1.f / l1;
    int row = qb * 64 + wm + (lane >> 2);
    int colb = h * HD + 2 * (lane & 3);
#pragma unroll
    for (int nt = 0; nt < 8; nt++) {
        *(float2*)&Y[(size_t)row * DMODEL + colb + nt * 8] =
            make_float2(o[nt][0] * i0, o[nt][1] * i0);
        *(float2*)&Y[(size_t)(row + 8) * DMODEL + colb + nt * 8] =
            make_float2(o[nt][2] * i1, o[nt][3] * i1);
    }
}

// ============================================================================
// Launch
// ============================================================================
extern "C" void kernel_launch(void* const* d_in, const int* in_sizes, int n_in,
                              void* d_out, int out_size)
{
    const float* x    = (const float*)d_in[0];
    const float* tcos = (const float*)d_in[1];
    const float* tsin = (const float*)d_in[2];
    const float* wq   = (const float*)d_in[3];
    const float* wk   = (const float*)d_in[4];
    const float* wv   = (const float*)d_in[5];
    const float* wo   = (const float*)d_in[6];
    float* out = (float*)d_out;

    float *Q, *K, *V, *Y;
    __nv_bfloat16 *Kh, *Kl, *Vh, *Vl;
    cudaGetSymbolAddress((void**)&Q, g_Q);
    cudaGetSymbolAddress((void**)&K, g_K);
    cudaGetSymbolAddress((void**)&V, g_V);
    cudaGetSymbolAddress((void**)&Y, g_Y);
    cudaGetSymbolAddress((void**)&Kh, g_Kh);
    cudaGetSymbolAddress((void**)&Kl, g_Kl);
    cudaGetSymbolAddress((void**)&Vh, g_Vh);
    cudaGetSymbolAddress((void**)&Vl, g_Vl);

    cudaFuncSetAttribute(gemm_mma, cudaFuncAttributeMaxDynamicSharedMemorySize, GSMEM);
    cudaFuncSetAttribute(attn_mma, cudaFuncAttributeMaxDynamicSharedMemorySize, ASMEM);

    dim3 gbig(DMODEL / 128, S_LEN / 128);   // (16,16)
    dim3 gkv(NKV_D / 128, S_LEN / 128);     // (4,16)

    gemm_mma<<<gbig, 256, GSMEM>>>(x, wq, Q, S_LEN, DMODEL, DMODEL);
    gemm_mma<<<gkv, 256, GSMEM>>>(x, wk, K, S_LEN, NKV_D, DMODEL);
    gemm_mma<<<gkv, 256, GSMEM>>>(x, wv, V, S_LEN, NKV_D, DMODEL);

    rope_split_kernel<<<(S_LEN * 256) / 256, 256>>>(K, V, tcos, tsin, Kh, Kl, Vh, Vl);

    attn_mma<<<dim3(32, NHEADS), 128, ASMEM>>>(Q, Kh, Kl, Vh, Vl, Y);

    gemm_mma<<<gbig, 256, GSMEM>>>(Y, wo, out, S_LEN, DMODEL, DMODEL);
}